// round 7
// baseline (speedup 1.0000x reference)
#include <cuda_runtime.h>
#include <cstdint>

#define NUM_BINS 31
#define THREADS 256
#define WARPS (THREADS / 32)
#define GRID_R 1184                 // reduce: 148 SMs * 8 blocks -> 1 wave @32regs
#define GRID_H 888                  // hist:   148 SMs * 6 blocks (smem-limited)
#define ROWS THREADS                // per-lane private sub-histograms
#define ROWW (NUM_BINS + 2)         // 33-wide rows: slot 31 = mx bucket, 32 pad

// ---------------- device-global scratch ------------------------------------
__device__ float  g_pmn[GRID_R];
__device__ float  g_pmx[GRID_R];
__device__ double g_ps [GRID_R];
__device__ double g_pss[GRID_R];
__device__ int    g_pnz[GRID_R];
__device__ int    g_counts[NUM_BINS];
__device__ unsigned int g_ticket;

// ---------------------------------------------------------------------------
// Pass 1: per-block min/max/sum/ss/nnz partials. Slim register footprint so
// 8 blocks/SM stay resident; MLP comes from 64 warps/SM each with one
// outstanding LDG.128. Block 0 zeroes g_counts + ticket.
__global__ void __launch_bounds__(THREADS, 8)
reduce_kernel(const float4* __restrict__ x4, int n4) {
    if (blockIdx.x == 0) {
        if (threadIdx.x < NUM_BINS) g_counts[threadIdx.x] = 0;
        if (threadIdx.x == NUM_BINS) g_ticket = 0u;
    }

    float mn =  __int_as_float(0x7F800000);
    float mx = -__int_as_float(0x7F800000);
    float s  = 0.f, ss = 0.f;
    int   nz = 0;

    const int T = GRID_R * THREADS;
    for (int i = blockIdx.x * THREADS + threadIdx.x; i < n4; i += T) {
        float4 a = x4[i];
        mn = fminf(mn, fminf(fminf(a.x, a.y), fminf(a.z, a.w)));
        mx = fmaxf(mx, fmaxf(fmaxf(a.x, a.y), fmaxf(a.z, a.w)));
        s += a.x; s += a.y; s += a.z; s += a.w;
        ss = fmaf(a.x, a.x, ss); ss = fmaf(a.y, a.y, ss);
        ss = fmaf(a.z, a.z, ss); ss = fmaf(a.w, a.w, ss);
        nz += (a.x != 0.f) + (a.y != 0.f) + (a.z != 0.f) + (a.w != 0.f);
    }

    #pragma unroll
    for (int o = 16; o > 0; o >>= 1) {
        mn = fminf(mn, __shfl_xor_sync(0xFFFFFFFFu, mn, o));
        mx = fmaxf(mx, __shfl_xor_sync(0xFFFFFFFFu, mx, o));
        s  += __shfl_xor_sync(0xFFFFFFFFu, s,  o);
        ss += __shfl_xor_sync(0xFFFFFFFFu, ss, o);
        nz += __shfl_xor_sync(0xFFFFFFFFu, nz, o);
    }

    __shared__ float  sh_mn[WARPS], sh_mx[WARPS];
    __shared__ double sh_s[WARPS],  sh_ss[WARPS];
    __shared__ int    sh_nz[WARPS];
    int lane = threadIdx.x & 31;
    int wid  = threadIdx.x >> 5;
    if (lane == 0) {
        sh_mn[wid] = mn; sh_mx[wid] = mx;
        sh_s[wid] = (double)s; sh_ss[wid] = (double)ss;
        sh_nz[wid] = nz;
    }
    __syncthreads();
    if (wid == 0) {
        mn = (lane < WARPS) ? sh_mn[lane] :  __int_as_float(0x7F800000);
        mx = (lane < WARPS) ? sh_mx[lane] : -__int_as_float(0x7F800000);
        double ds  = (lane < WARPS) ? sh_s[lane]  : 0.0;
        double dss = (lane < WARPS) ? sh_ss[lane] : 0.0;
        nz = (lane < WARPS) ? sh_nz[lane] : 0;
        #pragma unroll
        for (int o = 4; o > 0; o >>= 1) {
            mn = fminf(mn, __shfl_xor_sync(0xFFFFFFFFu, mn, o));
            mx = fmaxf(mx, __shfl_xor_sync(0xFFFFFFFFu, mx, o));
            ds  += __shfl_xor_sync(0xFFFFFFFFu, ds,  o);
            dss += __shfl_xor_sync(0xFFFFFFFFu, dss, o);
            nz  += __shfl_xor_sync(0xFFFFFFFFu, nz,  o);
        }
        if (lane == 0) {
            g_pmn[blockIdx.x] = mn;
            g_pmx[blockIdx.x] = mx;
            g_ps [blockIdx.x] = ds;
            g_pss[blockIdx.x] = dss;
            g_pnz[blockIdx.x] = nz;
        }
    }
}

// ---------------------------------------------------------------------------
// Pass 2: histogram. One private 33-word row PER THREAD (256 rows, 33.8 KB).
// Bank of (tid*33 + b) == (lane + b) mod 32, so lanes hitting the SAME bin go
// to 32 DISTINCT banks: the hot-bin case is conflict- and serialization-free.
// Lean binning (FFMA + trunc-F2I; slot 31 = val==mx bucket folded into bin 30).
__global__ void __launch_bounds__(THREADS, 6)
hist_kernel(const float4* __restrict__ x4, int n4,
            float* __restrict__ out, int n) {
    __shared__ int   s_hist[ROWS][ROWW];
    __shared__ float sh_f[WARPS];
    __shared__ float s_mn, s_mx;

    // --- reduce partial min/max (partials are L2-resident) ---
    {
        float mn =  __int_as_float(0x7F800000);
        float mx = -__int_as_float(0x7F800000);
        for (int i = threadIdx.x; i < GRID_R; i += THREADS) {
            mn = fminf(mn, g_pmn[i]);
            mx = fmaxf(mx, g_pmx[i]);
        }
        #pragma unroll
        for (int o = 16; o > 0; o >>= 1) {
            mn = fminf(mn, __shfl_xor_sync(0xFFFFFFFFu, mn, o));
            mx = fmaxf(mx, __shfl_xor_sync(0xFFFFFFFFu, mx, o));
        }
        int lane = threadIdx.x & 31, wid = threadIdx.x >> 5;
        if (lane == 0) sh_f[wid] = mn;
        __syncthreads();
        if (threadIdx.x == 0) {
            float m = sh_f[0];
            #pragma unroll
            for (int w = 1; w < WARPS; w++) m = fminf(m, sh_f[w]);
            s_mn = m;
        }
        __syncthreads();
        if (lane == 0) sh_f[wid] = mx;
        __syncthreads();
        if (threadIdx.x == 0) {
            float m = sh_f[0];
            #pragma unroll
            for (int w = 1; w < WARPS; w++) m = fmaxf(m, sh_f[w]);
            s_mx = m;
        }
        __syncthreads();
    }

    const float mn   = s_mn, mx = s_mx;
    const float step = (mx - mn) / (float)NUM_BINS;
    const float inv  = (float)NUM_BINS / (mx - mn);
    const float nb   = -mn * inv;   // bin coord = fmaf(val, inv, nb)

    for (int i = threadIdx.x; i < ROWS * ROWW; i += THREADS)
        ((int*)s_hist)[i] = 0;
    __syncthreads();

    const int T    = GRID_H * THREADS;
    const int gtid = blockIdx.x * THREADS + threadIdx.x;
    const int lane = threadIdx.x & 31;
    const int w    = threadIdx.x >> 5;
    int* const hrow = s_hist[threadIdx.x];

    // software-pipelined main loop: 2 float4 in flight per stage
    int i = gtid;
    if (i + T < n4) {
        float4 a = x4[i];
        float4 b = x4[i + T];
        i += 2 * T;
        for (; i + T < n4; i += 2 * T) {
            float4 a2 = x4[i];        // next-iteration loads issue first
            float4 b2 = x4[i + T];
            atomicAdd(&hrow[(int)fmaf(a.x, inv, nb)], 1);
            atomicAdd(&hrow[(int)fmaf(a.y, inv, nb)], 1);
            atomicAdd(&hrow[(int)fmaf(a.z, inv, nb)], 1);
            atomicAdd(&hrow[(int)fmaf(a.w, inv, nb)], 1);
            atomicAdd(&hrow[(int)fmaf(b.x, inv, nb)], 1);
            atomicAdd(&hrow[(int)fmaf(b.y, inv, nb)], 1);
            atomicAdd(&hrow[(int)fmaf(b.z, inv, nb)], 1);
            atomicAdd(&hrow[(int)fmaf(b.w, inv, nb)], 1);
            a = a2; b = b2;
        }
        atomicAdd(&hrow[(int)fmaf(a.x, inv, nb)], 1);
        atomicAdd(&hrow[(int)fmaf(a.y, inv, nb)], 1);
        atomicAdd(&hrow[(int)fmaf(a.z, inv, nb)], 1);
        atomicAdd(&hrow[(int)fmaf(a.w, inv, nb)], 1);
        atomicAdd(&hrow[(int)fmaf(b.x, inv, nb)], 1);
        atomicAdd(&hrow[(int)fmaf(b.y, inv, nb)], 1);
        atomicAdd(&hrow[(int)fmaf(b.z, inv, nb)], 1);
        atomicAdd(&hrow[(int)fmaf(b.w, inv, nb)], 1);
    }
    for (; i < n4; i += T) {
        float4 a = x4[i];
        atomicAdd(&hrow[(int)fmaf(a.x, inv, nb)], 1);
        atomicAdd(&hrow[(int)fmaf(a.y, inv, nb)], 1);
        atomicAdd(&hrow[(int)fmaf(a.z, inv, nb)], 1);
        atomicAdd(&hrow[(int)fmaf(a.w, inv, nb)], 1);
    }
    __syncthreads();

    for (int b = threadIdx.x; b < NUM_BINS; b += THREADS) {
        int t = 0;
        #pragma unroll 8
        for (int r = 0; r < ROWS; r++) t += s_hist[r][b];
        if (b == NUM_BINS - 1) {
            #pragma unroll 8
            for (int r = 0; r < ROWS; r++) t += s_hist[r][NUM_BINS]; // mx bucket
        }
        atomicAdd(&g_counts[b], t);
    }

    // --- last-block finalize ---
    __shared__ bool amLast;
    __threadfence();
    __syncthreads();
    if (threadIdx.x == 0)
        amLast = (atomicAdd(&g_ticket, 1u) == (unsigned)(GRID_H - 1));
    __syncthreads();
    if (!amLast) return;

    double ds = 0.0, dss = 0.0;
    long long nz = 0;
    for (int i2 = threadIdx.x; i2 < GRID_R; i2 += THREADS) {
        ds  += g_ps[i2];
        dss += g_pss[i2];
        nz  += g_pnz[i2];
    }
    #pragma unroll
    for (int o = 16; o > 0; o >>= 1) {
        ds  += __shfl_xor_sync(0xFFFFFFFFu, ds,  o);
        dss += __shfl_xor_sync(0xFFFFFFFFu, dss, o);
        nz  += __shfl_xor_sync(0xFFFFFFFFu, nz,  o);
    }
    __shared__ double sh_d[WARPS], sh_d2[WARPS];
    __shared__ long long sh_n[WARPS];
    if (lane == 0) { sh_d[w] = ds; sh_d2[w] = dss; sh_n[w] = nz; }
    __syncthreads();
    if (threadIdx.x == 0) {
        double tds = 0.0, tdss = 0.0; long long tnz = 0;
        #pragma unroll
        for (int ww = 0; ww < WARPS; ww++) { tds += sh_d[ww]; tdss += sh_d2[ww]; tnz += sh_n[ww]; }
        out[0] = mn;
        out[1] = mx;
        out[2] = (float)n;
        out[3] = (float)tnz;
        out[4] = (float)tds;
        out[5] = (float)tdss;
    }
    if (threadIdx.x < NUM_BINS) out[6 + threadIdx.x] = (float)g_counts[threadIdx.x];
    if (threadIdx.x <= NUM_BINS) {
        float e = __fadd_rn(mn, __fmul_rn((float)threadIdx.x, step));
        if (threadIdx.x == NUM_BINS) e = mx;
        out[6 + NUM_BINS + threadIdx.x] = e;
    }
}

// ---------------------------------------------------------------------------
extern "C" void kernel_launch(void* const* d_in, const int* in_sizes, int n_in,
                              void* d_out, int out_size) {
    const float* x = (const float*)d_in[0];
    int n  = in_sizes[0];
    int n4 = n / 4;
    float* out = (float*)d_out;

    reduce_kernel<<<GRID_R, THREADS>>>((const float4*)x, n4);
    hist_kernel  <<<GRID_H, THREADS>>>((const float4*)x, n4, out, n);
}

// round 8
// speedup vs baseline: 1.0645x; 1.0645x over previous
#include <cuda_runtime.h>
#include <cstdint>

#define NUM_BINS 31
#define THREADS 256
#define WARPS (THREADS / 32)
#define GRID_R 1184                 // reduce: 148 SMs * 8 blocks -> 1 wave @32regs
#define GRID_H 888                  // hist:   148 SMs * 6 blocks
#define COPIES 8
#define ROWS (WARPS * COPIES)       // 64 sub-histograms per block
#define ROWW (NUM_BINS + 2)         // 33-wide rows: slot 31 = mx bucket, 32 pad

// ---------------- device-global scratch ------------------------------------
__device__ float  g_pmn[GRID_R];
__device__ float  g_pmx[GRID_R];
__device__ double g_ps [GRID_R];
__device__ double g_pss[GRID_R];
__device__ int    g_pnz[GRID_R];
__device__ int    g_counts[NUM_BINS];
__device__ unsigned int g_ticket;

// ---------------------------------------------------------------------------
// Pass 1: per-block min/max/sum/ss/nnz partials. Slim register footprint so
// 8 blocks/SM stay resident; MLP comes from 64 warps/SM each with one
// outstanding LDG.128. Block 0 zeroes g_counts + ticket.
__global__ void __launch_bounds__(THREADS, 8)
reduce_kernel(const float4* __restrict__ x4, int n4) {
    if (blockIdx.x == 0) {
        if (threadIdx.x < NUM_BINS) g_counts[threadIdx.x] = 0;
        if (threadIdx.x == NUM_BINS) g_ticket = 0u;
    }

    float mn =  __int_as_float(0x7F800000);
    float mx = -__int_as_float(0x7F800000);
    float s  = 0.f, ss = 0.f;
    int   nz = 0;

    const int T = GRID_R * THREADS;
    for (int i = blockIdx.x * THREADS + threadIdx.x; i < n4; i += T) {
        float4 a = x4[i];
        mn = fminf(mn, fminf(fminf(a.x, a.y), fminf(a.z, a.w)));
        mx = fmaxf(mx, fmaxf(fmaxf(a.x, a.y), fmaxf(a.z, a.w)));
        s += a.x; s += a.y; s += a.z; s += a.w;
        ss = fmaf(a.x, a.x, ss); ss = fmaf(a.y, a.y, ss);
        ss = fmaf(a.z, a.z, ss); ss = fmaf(a.w, a.w, ss);
        nz += (a.x != 0.f) + (a.y != 0.f) + (a.z != 0.f) + (a.w != 0.f);
    }

    #pragma unroll
    for (int o = 16; o > 0; o >>= 1) {
        mn = fminf(mn, __shfl_xor_sync(0xFFFFFFFFu, mn, o));
        mx = fmaxf(mx, __shfl_xor_sync(0xFFFFFFFFu, mx, o));
        s  += __shfl_xor_sync(0xFFFFFFFFu, s,  o);
        ss += __shfl_xor_sync(0xFFFFFFFFu, ss, o);
        nz += __shfl_xor_sync(0xFFFFFFFFu, nz, o);
    }

    __shared__ float  sh_mn[WARPS], sh_mx[WARPS];
    __shared__ double sh_s[WARPS],  sh_ss[WARPS];
    __shared__ int    sh_nz[WARPS];
    int lane = threadIdx.x & 31;
    int wid  = threadIdx.x >> 5;
    if (lane == 0) {
        sh_mn[wid] = mn; sh_mx[wid] = mx;
        sh_s[wid] = (double)s; sh_ss[wid] = (double)ss;
        sh_nz[wid] = nz;
    }
    __syncthreads();
    if (wid == 0) {
        mn = (lane < WARPS) ? sh_mn[lane] :  __int_as_float(0x7F800000);
        mx = (lane < WARPS) ? sh_mx[lane] : -__int_as_float(0x7F800000);
        double ds  = (lane < WARPS) ? sh_s[lane]  : 0.0;
        double dss = (lane < WARPS) ? sh_ss[lane] : 0.0;
        nz = (lane < WARPS) ? sh_nz[lane] : 0;
        #pragma unroll
        for (int o = 4; o > 0; o >>= 1) {
            mn = fminf(mn, __shfl_xor_sync(0xFFFFFFFFu, mn, o));
            mx = fmaxf(mx, __shfl_xor_sync(0xFFFFFFFFu, mx, o));
            ds  += __shfl_xor_sync(0xFFFFFFFFu, ds,  o);
            dss += __shfl_xor_sync(0xFFFFFFFFu, dss, o);
            nz  += __shfl_xor_sync(0xFFFFFFFFu, nz,  o);
        }
        if (lane == 0) {
            g_pmn[blockIdx.x] = mn;
            g_pmx[blockIdx.x] = mx;
            g_ps [blockIdx.x] = ds;
            g_pss[blockIdx.x] = dss;
            g_pnz[blockIdx.x] = nz;
        }
    }
}

// ---------------------------------------------------------------------------
// Pass 2: histogram (round-6 configuration: best measured, 55.2us).
// 8 sub-histogram copies per warp (copy = lane&7): same-bin lanes spread over
// 8 addresses -> balances same-address serialization vs ATOMS spread-path
// cost (empirical optimum over 1/4/8/32 copies). Lean binning: FFMA +
// trunc-F2I, no clamp; slot 31 = val==mx bucket folded into bin 30 at merge.
// Next iteration's loads issue before current atomics (software pipeline).
__global__ void __launch_bounds__(THREADS, 6)
hist_kernel(const float4* __restrict__ x4, int n4,
            float* __restrict__ out, int n) {
    __shared__ int   s_hist[ROWS][ROWW];
    __shared__ float sh_f[WARPS];
    __shared__ float s_mn, s_mx;

    // --- reduce partial min/max (partials are L2-resident) ---
    {
        float mn =  __int_as_float(0x7F800000);
        float mx = -__int_as_float(0x7F800000);
        for (int i = threadIdx.x; i < GRID_R; i += THREADS) {
            mn = fminf(mn, g_pmn[i]);
            mx = fmaxf(mx, g_pmx[i]);
        }
        #pragma unroll
        for (int o = 16; o > 0; o >>= 1) {
            mn = fminf(mn, __shfl_xor_sync(0xFFFFFFFFu, mn, o));
            mx = fmaxf(mx, __shfl_xor_sync(0xFFFFFFFFu, mx, o));
        }
        int lane = threadIdx.x & 31, wid = threadIdx.x >> 5;
        if (lane == 0) sh_f[wid] = mn;
        __syncthreads();
        if (threadIdx.x == 0) {
            float m = sh_f[0];
            #pragma unroll
            for (int w = 1; w < WARPS; w++) m = fminf(m, sh_f[w]);
            s_mn = m;
        }
        __syncthreads();
        if (lane == 0) sh_f[wid] = mx;
        __syncthreads();
        if (threadIdx.x == 0) {
            float m = sh_f[0];
            #pragma unroll
            for (int w = 1; w < WARPS; w++) m = fmaxf(m, sh_f[w]);
            s_mx = m;
        }
        __syncthreads();
    }

    const float mn   = s_mn, mx = s_mx;
    const float step = (mx - mn) / (float)NUM_BINS;
    const float inv  = (float)NUM_BINS / (mx - mn);
    const float nb   = -mn * inv;   // bin coord = fmaf(val, inv, nb)

    for (int i = threadIdx.x; i < ROWS * ROWW; i += THREADS)
        ((int*)s_hist)[i] = 0;
    __syncthreads();

    const int T    = GRID_H * THREADS;
    const int gtid = blockIdx.x * THREADS + threadIdx.x;
    const int lane = threadIdx.x & 31;
    const int w    = threadIdx.x >> 5;
    int* const hrow = s_hist[(w << 3) | (lane & 7)];

    // software-pipelined main loop: 2 float4 in flight per stage
    int i = gtid;
    if (i + T < n4) {
        float4 a = x4[i];
        float4 b = x4[i + T];
        i += 2 * T;
        for (; i + T < n4; i += 2 * T) {
            float4 a2 = x4[i];        // next-iteration loads issue first
            float4 b2 = x4[i + T];
            atomicAdd(&hrow[(int)fmaf(a.x, inv, nb)], 1);
            atomicAdd(&hrow[(int)fmaf(a.y, inv, nb)], 1);
            atomicAdd(&hrow[(int)fmaf(a.z, inv, nb)], 1);
            atomicAdd(&hrow[(int)fmaf(a.w, inv, nb)], 1);
            atomicAdd(&hrow[(int)fmaf(b.x, inv, nb)], 1);
            atomicAdd(&hrow[(int)fmaf(b.y, inv, nb)], 1);
            atomicAdd(&hrow[(int)fmaf(b.z, inv, nb)], 1);
            atomicAdd(&hrow[(int)fmaf(b.w, inv, nb)], 1);
            a = a2; b = b2;
        }
        atomicAdd(&hrow[(int)fmaf(a.x, inv, nb)], 1);
        atomicAdd(&hrow[(int)fmaf(a.y, inv, nb)], 1);
        atomicAdd(&hrow[(int)fmaf(a.z, inv, nb)], 1);
        atomicAdd(&hrow[(int)fmaf(a.w, inv, nb)], 1);
        atomicAdd(&hrow[(int)fmaf(b.x, inv, nb)], 1);
        atomicAdd(&hrow[(int)fmaf(b.y, inv, nb)], 1);
        atomicAdd(&hrow[(int)fmaf(b.z, inv, nb)], 1);
        atomicAdd(&hrow[(int)fmaf(b.w, inv, nb)], 1);
    }
    for (; i < n4; i += T) {
        float4 a = x4[i];
        atomicAdd(&hrow[(int)fmaf(a.x, inv, nb)], 1);
        atomicAdd(&hrow[(int)fmaf(a.y, inv, nb)], 1);
        atomicAdd(&hrow[(int)fmaf(a.z, inv, nb)], 1);
        atomicAdd(&hrow[(int)fmaf(a.w, inv, nb)], 1);
    }
    __syncthreads();

    for (int b = threadIdx.x; b < NUM_BINS; b += THREADS) {
        int t = 0;
        #pragma unroll
        for (int r = 0; r < ROWS; r++) t += s_hist[r][b];
        if (b == NUM_BINS - 1) {
            #pragma unroll
            for (int r = 0; r < ROWS; r++) t += s_hist[r][NUM_BINS]; // mx bucket
        }
        atomicAdd(&g_counts[b], t);
    }

    // --- last-block finalize ---
    __shared__ bool amLast;
    __threadfence();
    __syncthreads();
    if (threadIdx.x == 0)
        amLast = (atomicAdd(&g_ticket, 1u) == (unsigned)(GRID_H - 1));
    __syncthreads();
    if (!amLast) return;

    double ds = 0.0, dss = 0.0;
    long long nz = 0;
    for (int i2 = threadIdx.x; i2 < GRID_R; i2 += THREADS) {
        ds  += g_ps[i2];
        dss += g_pss[i2];
        nz  += g_pnz[i2];
    }
    #pragma unroll
    for (int o = 16; o > 0; o >>= 1) {
        ds  += __shfl_xor_sync(0xFFFFFFFFu, ds,  o);
        dss += __shfl_xor_sync(0xFFFFFFFFu, dss, o);
        nz  += __shfl_xor_sync(0xFFFFFFFFu, nz,  o);
    }
    __shared__ double sh_d[WARPS], sh_d2[WARPS];
    __shared__ long long sh_n[WARPS];
    if (lane == 0) { sh_d[w] = ds; sh_d2[w] = dss; sh_n[w] = nz; }
    __syncthreads();
    if (threadIdx.x == 0) {
        double tds = 0.0, tdss = 0.0; long long tnz = 0;
        #pragma unroll
        for (int ww = 0; ww < WARPS; ww++) { tds += sh_d[ww]; tdss += sh_d2[ww]; tnz += sh_n[ww]; }
        out[0] = mn;
        out[1] = mx;
        out[2] = (float)n;
        out[3] = (float)tnz;
        out[4] = (float)tds;
        out[5] = (float)tdss;
    }
    if (threadIdx.x < NUM_BINS) out[6 + threadIdx.x] = (float)g_counts[threadIdx.x];
    if (threadIdx.x <= NUM_BINS) {
        float e = __fadd_rn(mn, __fmul_rn((float)threadIdx.x, step));
        if (threadIdx.x == NUM_BINS) e = mx;
        out[6 + NUM_BINS + threadIdx.x] = e;
    }
}

// ---------------------------------------------------------------------------
extern "C" void kernel_launch(void* const* d_in, const int* in_sizes, int n_in,
                              void* d_out, int out_size) {
    const float* x = (const float*)d_in[0];
    int n  = in_sizes[0];
    int n4 = n / 4;
    float* out = (float*)d_out;

    reduce_kernel<<<GRID_R, THREADS>>>((const float4*)x, n4);
    hist_kernel  <<<GRID_H, THREADS>>>((const float4*)x, n4, out, n);
}